// round 3
// baseline (speedup 1.0000x reference)
#include <cuda_runtime.h>

#define IMG_W 1024
#define IMG_H 1024

__global__ void zero_img_kernel(float4* __restrict__ img, int n4) {
    int i = blockIdx.x * blockDim.x + threadIdx.x;
    if (i < n4) img[i] = make_float4(0.f, 0.f, 0.f, 0.f);
}

__device__ __forceinline__ void red_v2(float* p, float a, float b) {
    // 8B-aligned vector reduction: one L2 lane for two adjacent pixels.
    asm volatile("red.global.add.v2.f32 [%0], {%1, %2};"
                 :: "l"(p), "f"(a), "f"(b) : "memory");
}

// sigma=0.1 => exponent -50*d^2. Only offsets {0,1} per dim are representable
// (others <= e^-50 relative ~ 5e-17, below fp32 ulp). Gate T=2e-4 on the
// normalized weight (measured rel_err 3e-5 at this gate, 30x under tolerance).
// x,y in [0,1) => xb,yb in [512,1023]; for even xb, xb+1 is always in range,
// so the even-x path pairs both x-taps into a single red.v2 (no gate needed —
// including a tiny tap only improves accuracy).
__global__ __launch_bounds__(256)
void splat_kernel(const float* __restrict__ xs,
                  const float* __restrict__ ys,
                  const float* __restrict__ vs,
                  float* __restrict__ img, int n)
{
    int i = blockIdx.x * blockDim.x + threadIdx.x;
    if (i >= n) return;

    float xp = (xs[i] + 1.0f) * 512.0f;   // exact in fp32
    float yp = (ys[i] + 1.0f) * 512.0f;
    float val = vs[i];

    float fxb = floorf(xp), fyb = floorf(yp);
    int   xb  = (int)fxb,   yb  = (int)fyb;
    float fx  = xp - fxb,   fy  = yp - fyb;   // [0,1)

    float gx = 1.0f - fx, gy = 1.0f - fy;
    float ex0 = __expf(-50.0f * fx * fx);
    float ex1 = __expf(-50.0f * gx * gx);
    float ey0 = __expf(-50.0f * fy * fy);
    float ey1 = __expf(-50.0f * gy * gy);

    float inv = 1.0f / ((ex0 + ex1) * (ey0 + ey1));
    float vi  = val * inv;

    float w00 = ex0 * ey0;
    float w10 = ex1 * ey0;
    float w01 = ex0 * ey1;
    float w11 = ex1 * ey1;

    const float T = 2e-4f;
    float t = T / inv;                 // gate in un-normalized space

    bool y1ok = (yb + 1 < IMG_H);
    float* p = img + yb * IMG_W + xb;

    if ((xb & 1) == 0) {
        // Paired path: one v2 lane per active row.
        red_v2(p, w00 * vi, w10 * vi);
        if (y1ok && (w01 > t || w11 > t))
            red_v2(p + IMG_W, w01 * vi, w11 * vi);
    } else {
        bool x1ok = (xb + 1 < IMG_W);
        if (w00 > t)                 atomicAdd(p,             w00 * vi);
        if (w10 > t && x1ok)         atomicAdd(p + 1,         w10 * vi);
        if (w01 > t && y1ok)         atomicAdd(p + IMG_W,     w01 * vi);
        if (w11 > t && x1ok && y1ok) atomicAdd(p + IMG_W + 1, w11 * vi);
    }
}

extern "C" void kernel_launch(void* const* d_in, const int* in_sizes, int n_in,
                              void* d_out, int out_size) {
    const float* xs = (const float*)d_in[0];
    const float* ys = (const float*)d_in[1];
    const float* vs = (const float*)d_in[2];
    float* img = (float*)d_out;
    int n = in_sizes[0];

    int n4 = out_size / 4;
    zero_img_kernel<<<(n4 + 255) / 256, 256>>>((float4*)img, n4);
    splat_kernel<<<(n + 255) / 256, 256>>>(xs, ys, vs, img, n);
}

// round 4
// speedup vs baseline: 1.0980x; 1.0980x over previous
#include <cuda_runtime.h>

#define IMG_W 1024
#define IMG_H 1024

__global__ void zero_img_kernel(float4* __restrict__ img, int n4) {
    int i = blockIdx.x * blockDim.x + threadIdx.x;
    if (i < n4) img[i] = make_float4(0.f, 0.f, 0.f, 0.f);
}

// sigma=0.1 => exponent -50*d^2. Of the 5 taps/dim only offsets {0,1} are
// representable (|d|>=1 raw weight <= e^-50, relative <= 5e-17 — below fp32
// ulp), so the 5-tap normalizing sum collapses to 2 exps per dim exactly.
// Splat gate T=1e-3 on the normalized weight: measured rel_err 3.0e-5 at
// T=2e-4, linear scaling => ~1.5e-4 here, ~6x under the 1e-3 tolerance.
// Scalar 4B REDG per tap: R3 showed the L2 atomic ALU is per-element, so
// vector atomics don't help; this form sits at the REDG element floor.
__global__ __launch_bounds__(256)
void splat_kernel(const float* __restrict__ xs,
                  const float* __restrict__ ys,
                  const float* __restrict__ vs,
                  float* __restrict__ img, int n)
{
    int i = blockIdx.x * blockDim.x + threadIdx.x;
    if (i >= n) return;

    float xp = (xs[i] + 1.0f) * 512.0f;   // (x - X0)/DX, exact in fp32
    float yp = (ys[i] + 1.0f) * 512.0f;
    float val = vs[i];

    float fxb = floorf(xp), fyb = floorf(yp);
    int   xb  = (int)fxb,   yb  = (int)fyb;
    float fx  = xp - fxb,   fy  = yp - fyb;   // [0,1)

    float gx = 1.0f - fx, gy = 1.0f - fy;
    float ex0 = __expf(-50.0f * fx * fx);
    float ex1 = __expf(-50.0f * gx * gx);
    float ey0 = __expf(-50.0f * fy * fy);
    float ey1 = __expf(-50.0f * gy * gy);

    float sxy = (ex0 + ex1) * (ey0 + ey1);
    float vi  = __fdividef(val, sxy);

    float w00 = ex0 * ey0;
    float w10 = ex1 * ey0;
    float w01 = ex0 * ey1;
    float w11 = ex1 * ey1;

    const float T = 1e-3f;
    float t = T * sxy;                 // gate in un-normalized space (no div)

    bool x1ok = (xb + 1 < IMG_W);
    bool y1ok = (yb + 1 < IMG_H);

    float* p = img + yb * IMG_W + xb;
    if (w00 > t)                 atomicAdd(p,             w00 * vi);
    if (w10 > t && x1ok)         atomicAdd(p + 1,         w10 * vi);
    if (w01 > t && y1ok)         atomicAdd(p + IMG_W,     w01 * vi);
    if (w11 > t && x1ok && y1ok) atomicAdd(p + IMG_W + 1, w11 * vi);
}

extern "C" void kernel_launch(void* const* d_in, const int* in_sizes, int n_in,
                              void* d_out, int out_size) {
    const float* xs = (const float*)d_in[0];
    const float* ys = (const float*)d_in[1];
    const float* vs = (const float*)d_in[2];
    float* img = (float*)d_out;
    int n = in_sizes[0];

    int n4 = out_size / 4;
    zero_img_kernel<<<(n4 + 255) / 256, 256>>>((float4*)img, n4);
    splat_kernel<<<(n + 255) / 256, 256>>>(xs, ys, vs, img, n);
}

// round 5
// speedup vs baseline: 1.1115x; 1.0122x over previous
#include <cuda_runtime.h>

#define IMG_W 1024
#define IMG_H 1024

__global__ void zero_img_kernel(float4* __restrict__ img, int n4) {
    int i = blockIdx.x * blockDim.x + threadIdx.x;
    if (i < n4) img[i] = make_float4(0.f, 0.f, 0.f, 0.f);
}

// sigma=0.1 => exponent -50*d^2. Of the 5 taps/dim only offsets {0,1} carry
// representable weight (|d|>=1 raw weight <= e^-50, relative <= 5e-17 — below
// fp32 ulp), so the 5-tap normalizing sum collapses to 2 exps/dim exactly.
// Gate T on normalized weight; measured rel_err is linear in T
// (2e-4 -> 3.0e-5, 1e-3 -> 1.5e-4), so T=2e-3 => ~3e-4, 3.3x under tolerance.
// Scalar 4B REDG per tap (R3: L2 atomic ALU is per-element; v2 regressed).
__device__ __forceinline__ void splat_one(float x, float y, float val,
                                          float* __restrict__ img)
{
    float xp = (x + 1.0f) * 512.0f;   // (x - X0)/DX, exact in fp32
    float yp = (y + 1.0f) * 512.0f;

    float fxb = floorf(xp), fyb = floorf(yp);
    int   xb  = (int)fxb,   yb  = (int)fyb;
    float fx  = xp - fxb,   fy  = yp - fyb;   // [0,1)

    float gx = 1.0f - fx, gy = 1.0f - fy;
    float ex0 = __expf(-50.0f * fx * fx);
    float ex1 = __expf(-50.0f * gx * gx);
    float ey0 = __expf(-50.0f * fy * fy);
    float ey1 = __expf(-50.0f * gy * gy);

    float sxy = (ex0 + ex1) * (ey0 + ey1);
    float vi  = __fdividef(val, sxy);

    float w00 = ex0 * ey0;
    float w10 = ex1 * ey0;
    float w01 = ex0 * ey1;
    float w11 = ex1 * ey1;

    const float T = 2e-3f;
    float t = T * sxy;                 // gate in un-normalized space

    bool x1ok = (xb + 1 < IMG_W);
    bool y1ok = (yb + 1 < IMG_H);

    float* p = img + yb * IMG_W + xb;
    if (w00 > t)                 atomicAdd(p,             w00 * vi);
    if (w10 > t && x1ok)         atomicAdd(p + 1,         w10 * vi);
    if (w01 > t && y1ok)         atomicAdd(p + IMG_W,     w01 * vi);
    if (w11 > t && x1ok && y1ok) atomicAdd(p + IMG_W + 1, w11 * vi);
}

// 4 points per thread, float4 loads: 4x fewer LDG warp-instrs, front-batched
// MLP so the LSU queue stays fed with REDGs.
__global__ __launch_bounds__(256)
void splat_kernel4(const float4* __restrict__ xs,
                   const float4* __restrict__ ys,
                   const float4* __restrict__ vs,
                   float* __restrict__ img, int n4)
{
    int i = blockIdx.x * blockDim.x + threadIdx.x;
    if (i >= n4) return;

    float4 x4 = xs[i];
    float4 y4 = ys[i];
    float4 v4 = vs[i];

    splat_one(x4.x, y4.x, v4.x, img);
    splat_one(x4.y, y4.y, v4.y, img);
    splat_one(x4.z, y4.z, v4.z, img);
    splat_one(x4.w, y4.w, v4.w, img);
}

// Scalar tail (n not divisible by 4).
__global__ void splat_kernel_tail(const float* __restrict__ xs,
                                  const float* __restrict__ ys,
                                  const float* __restrict__ vs,
                                  float* __restrict__ img, int start, int n)
{
    int i = start + blockIdx.x * blockDim.x + threadIdx.x;
    if (i < n) splat_one(xs[i], ys[i], vs[i], img);
}

extern "C" void kernel_launch(void* const* d_in, const int* in_sizes, int n_in,
                              void* d_out, int out_size) {
    const float* xs = (const float*)d_in[0];
    const float* ys = (const float*)d_in[1];
    const float* vs = (const float*)d_in[2];
    float* img = (float*)d_out;
    int n = in_sizes[0];

    int nimg4 = out_size / 4;
    zero_img_kernel<<<(nimg4 + 255) / 256, 256>>>((float4*)img, nimg4);

    int n4 = n / 4;
    if (n4 > 0)
        splat_kernel4<<<(n4 + 255) / 256, 256>>>((const float4*)xs,
                                                 (const float4*)ys,
                                                 (const float4*)vs, img, n4);
    int rem = n - n4 * 4;
    if (rem > 0)
        splat_kernel_tail<<<1, 32>>>(xs, ys, vs, img, n4 * 4, n);
}